// round 5
// baseline (speedup 1.0000x reference)
#include <cuda_runtime.h>
#include <cuda_bf16.h>
#include <cstdint>

#define HDIM 1024
#define SDIM 2048
#define VDIM 50257
#define NBOUND 25
#define MERGED 2048
#define NBLK 444
#define NTHR 512
#define G1TOT (NBLK * 13)       // 5772 vocab warps
#define R1 46176                // = G1TOT * 8 rows owned by group1

// ---------------- device scratch ----------------
__device__ __align__(16) float g_h[2][HDIM];
__device__ __align__(16) float g_q[HDIM];
__device__ __align__(16) float g_s[SDIM];
__device__ __align__(16) float g_ctx_part[8][HDIM];
__device__ __align__(16) float g_eproj[(size_t)SDIM * HDIM];          // 8 MB
__device__ __align__(16) __nv_bfloat16 g_wbf[(size_t)VDIM * MERGED];  // 206 MB (split-half layout)
__device__ __align__(16) float g_ub[VDIM];
__device__ __align__(16) float g_partA[VDIM];
__device__ __align__(16) float g_partB[VDIM];
__device__ unsigned g_M[2];
__device__ unsigned long long g_best[2];
__device__ unsigned g_bar_count, g_bar_phase;
__device__ unsigned g_sub_count, g_sub_phase;

// ---------------- helpers ----------------
__device__ __forceinline__ float warp_sum(float v) {
#pragma unroll
    for (int o = 16; o; o >>= 1) v += __shfl_xor_sync(0xffffffffu, v, o);
    return v;
}
__device__ __forceinline__ unsigned enc_f(float f) {
    unsigned b = __float_as_uint(f);
    return (b & 0x80000000u) ? ~b : (b | 0x80000000u);
}
__device__ __forceinline__ float dec_f(unsigned u) {
    unsigned b = (u & 0x80000000u) ? (u ^ 0x80000000u) : ~u;
    return __uint_as_float(b);
}
__device__ __forceinline__ float exp2_fast(float y) {
    y = fminf(fmaxf(y, -60.f), 60.f);
    float n = rintf(y);
    float f = y - n;
    float p = 1.5403530e-4f;
    p = fmaf(p, f, 1.3333558e-3f);
    p = fmaf(p, f, 9.6181291e-3f);
    p = fmaf(p, f, 5.5504109e-2f);
    p = fmaf(p, f, 2.4022651e-1f);
    p = fmaf(p, f, 6.9314718e-1f);
    p = fmaf(p, f, 1.0f);
    return __int_as_float(((int)n + 127) << 23) * p;
}
__device__ __forceinline__ float tanh_fast(float x) {
    float e = exp2_fast(x * 2.885390081777927f);
    return 1.f - 2.f / (e + 1.f);
}
__device__ __forceinline__ float sigmoid_fast(float x) {
    float e = exp2_fast(-1.4426950408889634f * x);
    return 1.f / (1.f + e);
}

// grid-wide barrier (all 16 warps of every block)
__device__ __forceinline__ void gsync(unsigned& tgt) {
    __syncthreads();
    if (threadIdx.x == 0) {
        __threadfence();
        unsigned v = atomicAdd(&g_bar_count, 1u);
        if (v == NBLK - 1) {
            g_bar_count = 0;
            asm volatile("st.release.gpu.u32 [%0], %1;" :: "l"(&g_bar_phase), "r"(tgt) : "memory");
        } else {
            unsigned p;
            do {
                asm volatile("ld.acquire.gpu.u32 %0, [%1];" : "=r"(p) : "l"(&g_bar_phase) : "memory");
            } while ((int)(p - tgt) < 0);
        }
    }
    __syncthreads();
    tgt++;
}

// sub-grid barrier among warps 0-2 of every block (96 threads/block)
__device__ __forceinline__ void subsync(unsigned& stgt) {
    asm volatile("bar.sync 4, 96;" ::: "memory");
    if (threadIdx.x == 0) {
        __threadfence();
        unsigned v = atomicAdd(&g_sub_count, 1u);
        if (v == NBLK - 1) {
            g_sub_count = 0;
            asm volatile("st.release.gpu.u32 [%0], %1;" :: "l"(&g_sub_phase), "r"(stgt) : "memory");
        } else {
            unsigned p;
            do {
                asm volatile("ld.acquire.gpu.u32 %0, [%1];" : "=r"(p) : "l"(&g_sub_phase) : "memory");
            } while ((int)(p - stgt) < 0);
        }
    }
    asm volatile("bar.sync 4, 96;" ::: "memory");
    stgt++;
}

// ---------------- the persistent mega-kernel ----------------
__global__ __launch_bounds__(NTHR, 3) void k_mega(
    const float* __restrict__ hidden, const float* __restrict__ emb,
    const float* __restrict__ emb_table,
    const float* __restrict__ W_ih, const float* __restrict__ W_hh,
    const float* __restrict__ b_ih, const float* __restrict__ b_hh,
    const float* __restrict__ We, const float* __restrict__ Wq,
    const float* __restrict__ ba, const float* __restrict__ va,
    const float* __restrict__ Wout, const float* __restrict__ bout,
    float* __restrict__ out)
{
    __shared__ __align__(16) float s_As[128 * 36];   // eproj A tile
    __shared__ __align__(16) float s_Bs[64 * 33];    // eproj B tile
    __shared__ __align__(16) float s_ms[MERGED];     // merge vector
    __shared__ float s_gru[3][4][6];
    __shared__ float s_sm[8];
    __shared__ float s_red[16];
    __shared__ int s_cand[32];
    __shared__ int s_cnt;
    __shared__ int s_word;

    const int tid = threadIdx.x;
    const int blk = blockIdx.x;
    const int w = tid >> 5, lane = tid & 31;

    unsigned tgt  = *((volatile unsigned*)&g_bar_phase) + 1;
    unsigned stgt = *((volatile unsigned*)&g_sub_phase) + 1;

    // ---------- phase 0: init + (eproj || quant) ----------
    if (blk == 0 && tid < 2) { g_M[tid] = 0u; g_best[tid] = 0ull; }
    if (blk == 1) {
        for (int i = tid; i < HDIM; i += NTHR) g_h[0][i] = hidden[i];
    }

    if (blk < 256) {
        const int ts0 = (blk >> 4) * 128;
        const int ta0 = (blk & 15) * 64;
        const int ts = tid >> 4;
        const int ta = tid & 15;
        float acc[4][4];
#pragma unroll
        for (int i = 0; i < 4; i++)
#pragma unroll
            for (int j = 0; j < 4; j++) acc[i][j] = 0.f;
        for (int kt = 0; kt < 1024; kt += 32) {
#pragma unroll
            for (int r = 0; r < 8; r++) {
                int e0 = tid + NTHR * r;
                int si = e0 >> 5, kk = e0 & 31;
                s_As[si * 36 + kk] = emb[(size_t)(ts0 + si) * 1024 + kt + kk];
            }
#pragma unroll
            for (int r = 0; r < 4; r++) {
                int e0 = tid + NTHR * r;
                int ai = e0 >> 5, kk = e0 & 31;
                s_Bs[ai * 33 + kk] = We[(size_t)(ta0 + ai) * 1024 + kt + kk];
            }
            __syncthreads();
#pragma unroll
            for (int k = 0; k < 32; k++) {
                float a0 = s_As[ts * 36 + k];
                float a1 = s_As[(ts + 32) * 36 + k];
                float a2 = s_As[(ts + 64) * 36 + k];
                float a3 = s_As[(ts + 96) * 36 + k];
                float b0 = s_Bs[(ta * 4 + 0) * 33 + k];
                float b1 = s_Bs[(ta * 4 + 1) * 33 + k];
                float b2 = s_Bs[(ta * 4 + 2) * 33 + k];
                float b3 = s_Bs[(ta * 4 + 3) * 33 + k];
                acc[0][0] = fmaf(a0, b0, acc[0][0]); acc[0][1] = fmaf(a0, b1, acc[0][1]);
                acc[0][2] = fmaf(a0, b2, acc[0][2]); acc[0][3] = fmaf(a0, b3, acc[0][3]);
                acc[1][0] = fmaf(a1, b0, acc[1][0]); acc[1][1] = fmaf(a1, b1, acc[1][1]);
                acc[1][2] = fmaf(a1, b2, acc[1][2]); acc[1][3] = fmaf(a1, b3, acc[1][3]);
                acc[2][0] = fmaf(a2, b0, acc[2][0]); acc[2][1] = fmaf(a2, b1, acc[2][1]);
                acc[2][2] = fmaf(a2, b2, acc[2][2]); acc[2][3] = fmaf(a2, b3, acc[2][3]);
                acc[3][0] = fmaf(a3, b0, acc[3][0]); acc[3][1] = fmaf(a3, b1, acc[3][1]);
                acc[3][2] = fmaf(a3, b2, acc[3][2]); acc[3][3] = fmaf(a3, b3, acc[3][3]);
            }
            __syncthreads();
        }
        float4 bb = __ldg((const float4*)(ba + ta0) + ta);
#pragma unroll
        for (int i = 0; i < 4; i++) {
            float4 o = make_float4(acc[i][0] + bb.x, acc[i][1] + bb.y,
                                   acc[i][2] + bb.z, acc[i][3] + bb.w);
            *(float4*)&g_eproj[(size_t)(ts0 + ts + 32 * i) * 1024 + ta0 + ta * 4] = o;
        }
    } else {
        // quant to SPLIT-HALF layout: h-halves contiguous, then ctx-halves
        const size_t n8 = (size_t)VDIM * MERGED / 8;   // 8-bf16 chunks
        const size_t CTXOFF4 = (size_t)VDIM * 128;     // uint4-index of ctx region
        for (size_t idx = (size_t)(blk - 256) * NTHR + tid; idx < n8;
             idx += (size_t)(NBLK - 256) * NTHR) {
            size_t v = idx >> 8;
            int c8 = (int)(idx & 255);                 // 8-col group within row
            const float4* p = (const float4*)Wout + idx * 2;
            float4 a = __ldcs(p);
            float4 b = __ldcs(p + 1);
            uint4 o;
            *(__nv_bfloat162*)&o.x = __nv_bfloat162(__float2bfloat16(a.x), __float2bfloat16(a.y));
            *(__nv_bfloat162*)&o.y = __nv_bfloat162(__float2bfloat16(a.z), __float2bfloat16(a.w));
            *(__nv_bfloat162*)&o.z = __nv_bfloat162(__float2bfloat16(b.x), __float2bfloat16(b.y));
            *(__nv_bfloat162*)&o.w = __nv_bfloat162(__float2bfloat16(b.z), __float2bfloat16(b.w));
            size_t dst = (c8 < 128) ? v * 128 + c8 : CTXOFF4 + v * 128 + (c8 - 128);
            __stcs((uint4*)g_wbf + dst, o);
        }
    }
    gsync(tgt);

    // ---------- decode loop ----------
    int word = 1;  // SOS
    for (int t = 0; t < NBOUND; t++) {
        const int par = t & 1;
        const int pold = par, pnew = par ^ 1;

        // ---- GRU: 12 warps/block, 3 rows/block, k-split 4 ----
        {
            int g = w >> 2, sub = w & 3;
            int j = blk * 3 + g;
            if (g < 3 && j < 1024) {
                int k4 = sub * 64;   // float4 offset of k-slice
                const float4* xv = (const float4*)(emb_table + (size_t)word * 1024) + k4;
                const float4* hv = (const float4*)g_h[pold] + k4;
                const float4* m0 = (const float4*)(W_ih + (size_t)j * 1024) + k4;
                const float4* m1 = (const float4*)(W_ih + (size_t)(1024 + j) * 1024) + k4;
                const float4* m2 = (const float4*)(W_ih + (size_t)(2048 + j) * 1024) + k4;
                const float4* m3 = (const float4*)(W_hh + (size_t)j * 1024) + k4;
                const float4* m4p = (const float4*)(W_hh + (size_t)(1024 + j) * 1024) + k4;
                const float4* m5 = (const float4*)(W_hh + (size_t)(2048 + j) * 1024) + k4;
                float a0 = 0, a1 = 0, a2 = 0, a3 = 0, a4 = 0, a5 = 0;
#pragma unroll
                for (int i = 0; i < 2; i++) {
                    int k = lane + 32 * i;
                    float4 x = __ldg(xv + k);
                    float4 h = __ldcg(hv + k);
                    float4 m;
                    m = __ldg(m0 + k); a0 = fmaf(m.x, x.x, a0); a0 = fmaf(m.y, x.y, a0); a0 = fmaf(m.z, x.z, a0); a0 = fmaf(m.w, x.w, a0);
                    m = __ldg(m1 + k); a1 = fmaf(m.x, x.x, a1); a1 = fmaf(m.y, x.y, a1); a1 = fmaf(m.z, x.z, a1); a1 = fmaf(m.w, x.w, a1);
                    m = __ldg(m2 + k); a2 = fmaf(m.x, x.x, a2); a2 = fmaf(m.y, x.y, a2); a2 = fmaf(m.z, x.z, a2); a2 = fmaf(m.w, x.w, a2);
                    m = __ldg(m3 + k); a3 = fmaf(m.x, h.x, a3); a3 = fmaf(m.y, h.y, a3); a3 = fmaf(m.z, h.z, a3); a3 = fmaf(m.w, h.w, a3);
                    m = __ldg(m4p + k); a4 = fmaf(m.x, h.x, a4); a4 = fmaf(m.y, h.y, a4); a4 = fmaf(m.z, h.z, a4); a4 = fmaf(m.w, h.w, a4);
                    m = __ldg(m5 + k); a5 = fmaf(m.x, h.x, a5); a5 = fmaf(m.y, h.y, a5); a5 = fmaf(m.z, h.z, a5); a5 = fmaf(m.w, h.w, a5);
                }
                a0 = warp_sum(a0); a1 = warp_sum(a1); a2 = warp_sum(a2);
                a3 = warp_sum(a3); a4 = warp_sum(a4); a5 = warp_sum(a5);
                if (lane == 0) {
                    s_gru[g][sub][0] = a0; s_gru[g][sub][1] = a1; s_gru[g][sub][2] = a2;
                    s_gru[g][sub][3] = a3; s_gru[g][sub][4] = a4; s_gru[g][sub][5] = a5;
                }
            }
            __syncthreads();
            if (tid < 3) {
                int jo = blk * 3 + tid;
                if (jo < 1024) {
                    float D[6];
#pragma unroll
                    for (int d = 0; d < 6; d++)
                        D[d] = s_gru[tid][0][d] + s_gru[tid][1][d] + s_gru[tid][2][d] + s_gru[tid][3][d];
                    float gr = D[0] + __ldg(&b_ih[jo]);
                    float gz = D[1] + __ldg(&b_ih[1024 + jo]);
                    float gn = D[2] + __ldg(&b_ih[2048 + jo]);
                    float hr = D[3] + __ldg(&b_hh[jo]);
                    float hz = D[4] + __ldg(&b_hh[1024 + jo]);
                    float hn = D[5] + __ldg(&b_hh[2048 + jo]);
                    float r = sigmoid_fast(gr + hr);
                    float z = sigmoid_fast(gz + hz);
                    float n = tanh_fast(gn + r * hn);
                    float hold = __ldcg(&g_h[pold][jo]);
                    __stcg(&g_h[pnew][jo], (1.f - z) * n + z * hold);
                }
            }
        }
        gsync(tgt);
        if (blk == 0 && tid == 0) {
            atomicExch(&g_M[par ^ 1], 0u);
            atomicExch(&g_best[par ^ 1], 0ull);
        }

        // ---- split phase: warps 0-2 small chain | warps 3-15 vocab h-half ----
        if (w < 3) {
            // q
            {
                int a = blk * 3 + w;
                if (a < 1024) {
                    const float4* mq = (const float4*)(Wq + (size_t)a * 1024);
                    const float4* hv = (const float4*)g_h[pnew];
                    float acc = 0.f;
#pragma unroll
                    for (int i = 0; i < 8; i++) {
                        int k = lane + 32 * i;
                        float4 m = __ldg(mq + k);
                        float4 h = __ldcg(hv + k);
                        acc = fmaf(m.x, h.x, acc); acc = fmaf(m.y, h.y, acc);
                        acc = fmaf(m.z, h.z, acc); acc = fmaf(m.w, h.w, acc);
                    }
                    acc = warp_sum(acc);
                    if (lane == 0) __stcg(&g_q[a], acc);
                }
            }
            subsync(stgt);
            // s
#pragma unroll
            for (int r = 0; r < 2; r++) {
                int j = (blk * 3 + w) + 1332 * r;
                if (j < 2048) {
                    const float4* ep = (const float4*)(g_eproj + (size_t)j * 1024);
                    const float4* qv = (const float4*)g_q;
                    const float4* vv = (const float4*)va;
                    float acc = 0.f;
#pragma unroll 4
                    for (int i = 0; i < 8; i++) {
                        int k = lane + 32 * i;
                        float4 e4 = __ldg(ep + k);
                        float4 q4 = __ldcg(qv + k);
                        float4 v4 = __ldg(vv + k);
                        acc = fmaf(tanh_fast(e4.x + q4.x), v4.x, acc);
                        acc = fmaf(tanh_fast(e4.y + q4.y), v4.y, acc);
                        acc = fmaf(tanh_fast(e4.z + q4.z), v4.z, acc);
                        acc = fmaf(tanh_fast(e4.w + q4.w), v4.w, acc);
                    }
                    acc = warp_sum(acc);
                    if (lane == 0) __stcg(&g_s[j], acc);
                }
            }
            subsync(stgt);
            // softmax stats + ctx partial + weights output (blocks < 128)
            if (blk < 128) {
                float lm = -3.4e38f;
                for (int i = tid; i < 2048; i += 96) lm = fmaxf(lm, __ldcg(&g_s[i]));
#pragma unroll
                for (int o = 16; o; o >>= 1) lm = fmaxf(lm, __shfl_xor_sync(0xffffffffu, lm, o));
                if (lane == 0) s_sm[w] = lm;
                asm volatile("bar.sync 5, 96;" ::: "memory");
                float m = fmaxf(s_sm[0], fmaxf(s_sm[1], s_sm[2]));
                float ls = 0.f;
                for (int i = tid; i < 2048; i += 96) ls += expf(__ldcg(&g_s[i]) - m);
                ls = warp_sum(ls);
                if (lane == 0) s_sm[3 + w] = ls;
                asm volatile("bar.sync 5, 96;" ::: "memory");
                float inv = 1.f / (s_sm[3] + s_sm[4] + s_sm[5]);
                if (blk == 0) {
                    size_t base = (size_t)NBOUND + (size_t)t * SDIM;
                    for (int i = tid; i < 2048; i += 96)
                        out[base + i] = expf(__ldcg(&g_s[i]) - m) * inv;
                }
                int sc = blk >> 4, ac = blk & 15;
                if (tid < 64) {
                    int aa = ac * 64 + tid;
                    float acc = 0.f;
                    int sb = sc * 256;
#pragma unroll 4
                    for (int ss = 0; ss < 256; ss++) {
                        int s = sb + ss;
                        float wv = expf(__ldcg(&g_s[s]) - m) * inv;
                        acc = fmaf(wv, __ldg(&emb[(size_t)s * 1024 + aa]), acc);
                    }
                    __stcg(&g_ctx_part[sc][aa], acc);
                }
            }
        } else {
            // vocab warps: build h-half of merge, then h-half dots
            int vt = tid - 96;
            for (int i = vt; i < 1024; i += 416) s_ms[i] = __ldcg(&g_h[pnew][i]);
            asm volatile("bar.sync 2, 416;" ::: "memory");
            const float4* m4 = (const float4*)s_ms;
            int q1 = blk * 13 + (w - 3);
#pragma unroll 2
            for (int r = 0; r < 8; r++) {
                int v = q1 + G1TOT * r;
                const unsigned long long* r8 = (const unsigned long long*)g_wbf + (size_t)v * 256;
                float acc = 0.f, ab = 0.f;
#pragma unroll
                for (int i = 0; i < 8; i++) {
                    int j = lane + 32 * i;
                    unsigned long long u = __ldcs(r8 + j);
                    float4 mm = m4[j];
                    unsigned lo = (unsigned)u, hi = (unsigned)(u >> 32);
                    float2 f0 = __bfloat1622float2(*(__nv_bfloat162*)&lo);
                    float2 f1 = __bfloat1622float2(*(__nv_bfloat162*)&hi);
                    acc = fmaf(f0.x, mm.x, acc); ab = fmaf(fabsf(f0.x), fabsf(mm.x), ab);
                    acc = fmaf(f0.y, mm.y, acc); ab = fmaf(fabsf(f0.y), fabsf(mm.y), ab);
                    acc = fmaf(f1.x, mm.z, acc); ab = fmaf(fabsf(f1.x), fabsf(mm.z), ab);
                    acc = fmaf(f1.y, mm.w, acc); ab = fmaf(fabsf(f1.y), fabsf(mm.w), ab);
                }
                acc = warp_sum(acc);
                ab = warp_sum(ab);
                if (lane == 0) { g_partA[v] = acc; g_partB[v] = ab; }
            }
        }
        gsync(tgt);   // join: ctx done + h-half done

        // ---- phase 2: full merge + ctx-half / full-row dots + bound ----
        for (int i = tid; i < 1024; i += NTHR) s_ms[i] = __ldcg(&g_h[pnew][i]);
        for (int i = tid; i < 1024; i += NTHR) {
            float c = 0.f;
#pragma unroll
            for (int p = 0; p < 8; p++) c += __ldcg(&g_ctx_part[p][i]);
            s_ms[1024 + i] = c;
        }
        __syncthreads();
        const float4* m4 = (const float4*)s_ms;
        const size_t CTXOFF8 = (size_t)VDIM * 256;   // uint64-index of ctx region
        float wmax = -3.4e38f;
        if (w >= 3) {
            int q1 = blk * 13 + (w - 3);
#pragma unroll 2
            for (int r = 0; r < 8; r++) {
                int v = q1 + G1TOT * r;
                const unsigned long long* r8 =
                    (const unsigned long long*)g_wbf + CTXOFF8 + (size_t)v * 256;
                float acc = 0.f, ab = 0.f;
#pragma unroll
                for (int i = 0; i < 8; i++) {
                    int j = lane + 32 * i;
                    unsigned long long u = __ldcs(r8 + j);
                    float4 mm = m4[256 + j];
                    unsigned lo = (unsigned)u, hi = (unsigned)(u >> 32);
                    float2 f0 = __bfloat1622float2(*(__nv_bfloat162*)&lo);
                    float2 f1 = __bfloat1622float2(*(__nv_bfloat162*)&hi);
                    acc = fmaf(f0.x, mm.x, acc); ab = fmaf(fabsf(f0.x), fabsf(mm.x), ab);
                    acc = fmaf(f0.y, mm.y, acc); ab = fmaf(fabsf(f0.y), fabsf(mm.y), ab);
                    acc = fmaf(f1.x, mm.z, acc); ab = fmaf(fabsf(f1.x), fabsf(mm.z), ab);
                    acc = fmaf(f1.y, mm.w, acc); ab = fmaf(fabsf(f1.y), fabsf(mm.w), ab);
                }
                acc = warp_sum(acc);
                ab = warp_sum(ab);
                if (lane == 0) {
                    float A = acc + g_partA[v] + __ldg(&bout[v]);
                    float ab_t = ab + g_partB[v];
                    float B = fmaf(ab_t, 0.00392f, 2e-4f);
                    __stcg(&g_ub[v], A + B);
                    wmax = fmaxf(wmax, A - B);
                }
            }
        } else {
            int q2 = blk * 3 + w;
#pragma unroll
            for (int r = 0; r < 4; r++) {
                int v = R1 + q2 + 1332 * r;
                if (v < VDIM) {
                    const unsigned long long* rh = (const unsigned long long*)g_wbf + (size_t)v * 256;
                    const unsigned long long* rc = (const unsigned long long*)g_wbf + CTXOFF8 + (size_t)v * 256;
                    float acc = 0.f, ab = 0.f;
#pragma unroll
                    for (int i = 0; i < 8; i++) {
                        int j = lane + 32 * i;
                        unsigned long long u = __ldcs(rh + j);
                        float4 mm = m4[j];
                        unsigned lo = (unsigned)u, hi = (unsigned)(u >> 32);
                        float2 f0 = __bfloat1622float2(*(__nv_bfloat162*)&lo);
                        float2 f1 = __bfloat1622float2(*(__nv_bfloat162*)&hi);
                        acc = fmaf(f0.x, mm.x, acc); ab = fmaf(fabsf(f0.x), fabsf(mm.x), ab);
                        acc = fmaf(f0.y, mm.y, acc); ab = fmaf(fabsf(f0.y), fabsf(mm.y), ab);
                        acc = fmaf(f1.x, mm.z, acc); ab = fmaf(fabsf(f1.x), fabsf(mm.z), ab);
                        acc = fmaf(f1.y, mm.w, acc); ab = fmaf(fabsf(f1.y), fabsf(mm.w), ab);
                    }
#pragma unroll
                    for (int i = 0; i < 8; i++) {
                        int j = lane + 32 * i;
                        unsigned long long u = __ldcs(rc + j);
                        float4 mm = m4[256 + j];
                        unsigned lo = (unsigned)u, hi = (unsigned)(u >> 32);
                        float2 f0 = __bfloat1622float2(*(__nv_bfloat162*)&lo);
                        float2 f1 = __bfloat1622float2(*(__nv_bfloat162*)&hi);
                        acc = fmaf(f0.x, mm.x, acc); ab = fmaf(fabsf(f0.x), fabsf(mm.x), ab);
                        acc = fmaf(f0.y, mm.y, acc); ab = fmaf(fabsf(f0.y), fabsf(mm.y), ab);
                        acc = fmaf(f1.x, mm.z, acc); ab = fmaf(fabsf(f1.x), fabsf(mm.z), ab);
                        acc = fmaf(f1.y, mm.w, acc); ab = fmaf(fabsf(f1.y), fabsf(mm.w), ab);
                    }
                    acc = warp_sum(acc);
                    ab = warp_sum(ab);
                    if (lane == 0) {
                        float A = acc + __ldg(&bout[v]);
                        float B = fmaf(ab, 0.00392f, 2e-4f);
                        __stcg(&g_ub[v], A + B);
                        wmax = fmaxf(wmax, A - B);
                    }
                }
            }
        }
        // block-local bound max -> single atomic
#pragma unroll
        for (int o = 16; o; o >>= 1) wmax = fmaxf(wmax, __shfl_xor_sync(0xffffffffu, wmax, o));
        if (lane == 0) s_red[w] = wmax;
        __syncthreads();
        if (tid == 0) {
            float bm = s_red[0];
#pragma unroll
            for (int k = 1; k < 16; k++) bm = fmaxf(bm, s_red[k]);
            atomicMax(&g_M[par], enc_f(bm));
        }
        gsync(tgt);

        // ---- scan + exact fp32 rescore ----
        if (tid == 0) s_cnt = 0;
        __syncthreads();
        {
            float thr = dec_f(__ldcg(&g_M[par]));
            int i = blk * NTHR + tid;
            if (i < VDIM && __ldcg(&g_ub[i]) >= thr) {
                int p = atomicAdd(&s_cnt, 1);
                if (p < 32) s_cand[p] = i;
            }
        }
        __syncthreads();
        int nc = min(s_cnt, 32);
        for (int c = 0; c < nc; c++) {
            int v = s_cand[c];
            float4 rr = __ldg((const float4*)(Wout + (size_t)v * MERGED) + tid);
            float4 mm = m4[tid];
            float a = fmaf(rr.x, mm.x, fmaf(rr.y, mm.y, fmaf(rr.z, mm.z, rr.w * mm.w)));
            a = warp_sum(a);
            if (lane == 0) s_red[w] = a;
            __syncthreads();
            if (tid == 0) {
                float L = 0.f;
#pragma unroll
                for (int k = 0; k < 16; k++) L += s_red[k];
                L += __ldg(&bout[v]);
                unsigned long long pk =
                    ((unsigned long long)enc_f(L) << 32) |
                    (unsigned long long)(0xFFFFFFFFu - (unsigned)v);
                atomicMax(&g_best[par], pk);
            }
            __syncthreads();
        }
        gsync(tgt);

        if (tid == 0) {
            unsigned long long pk = __ldcg(&g_best[par]);
            int wd = (int)(0xFFFFFFFFu - (unsigned)(pk & 0xFFFFFFFFull));
            s_word = wd;
            if (blk == 0) out[t] = (float)wd;
        }
        __syncthreads();
        word = s_word;
    }
}

// ---------------- launch ----------------
extern "C" void kernel_launch(void* const* d_in, const int* in_sizes, int n_in,
                              void* d_out, int out_size) {
    const float* hidden     = (const float*)d_in[0];
    const float* embeddings = (const float*)d_in[1];
    const float* emb_table  = (const float*)d_in[2];
    const float* W_ih       = (const float*)d_in[3];
    const float* W_hh       = (const float*)d_in[4];
    const float* b_ih       = (const float*)d_in[5];
    const float* b_hh       = (const float*)d_in[6];
    const float* W_e        = (const float*)d_in[7];
    const float* W_q        = (const float*)d_in[8];
    const float* b_a        = (const float*)d_in[9];
    const float* v_a        = (const float*)d_in[10];
    const float* W_out      = (const float*)d_in[11];
    const float* b_out      = (const float*)d_in[12];
    float* out = (float*)d_out;

    k_mega<<<NBLK, NTHR>>>(hidden, embeddings, emb_table, W_ih, W_hh, b_ih, b_hh,
                           W_e, W_q, b_a, v_a, W_out, b_out, out);
}

// round 6
// speedup vs baseline: 1.9590x; 1.9590x over previous
#include <cuda_runtime.h>
#include <cuda_bf16.h>
#include <cstdint>

#define HDIM 1024
#define SDIM 2048
#define VDIM 50257
#define NBOUND 25
#define MERGED 2048
#define NBLK 296           // 148 SMs x 2 co-resident blocks
#define NTHR 512
#define NWTOT (NBLK * 16)  // 4736 warps

// ---------------- device scratch ----------------
__device__ __align__(16) float g_h[2][HDIM];
__device__ __align__(16) float g_q[HDIM];
__device__ __align__(16) float g_s[SDIM];
__device__ __align__(16) float g_ctx_part[8][HDIM];
__device__ __align__(16) float g_eproj[(size_t)SDIM * HDIM];          // 8 MB
__device__ __align__(16) __nv_bfloat16 g_wbf[(size_t)VDIM * MERGED];  // 206 MB
__device__ __align__(16) float g_ub[VDIM];
__device__ unsigned g_M[2];
__device__ unsigned long long g_best[2];
__device__ unsigned g_bar_count, g_bar_phase;

// ---------------- helpers ----------------
__device__ __forceinline__ float warp_sum(float v) {
#pragma unroll
    for (int o = 16; o; o >>= 1) v += __shfl_xor_sync(0xffffffffu, v, o);
    return v;
}
__device__ __forceinline__ unsigned enc_f(float f) {
    unsigned b = __float_as_uint(f);
    return (b & 0x80000000u) ? ~b : (b | 0x80000000u);
}
__device__ __forceinline__ float dec_f(unsigned u) {
    unsigned b = (u & 0x80000000u) ? (u ^ 0x80000000u) : ~u;
    return __uint_as_float(b);
}
__device__ __forceinline__ float exp2_fast(float y) {
    y = fminf(fmaxf(y, -60.f), 60.f);
    float n = rintf(y);
    float f = y - n;
    float p = 1.5403530e-4f;
    p = fmaf(p, f, 1.3333558e-3f);
    p = fmaf(p, f, 9.6181291e-3f);
    p = fmaf(p, f, 5.5504109e-2f);
    p = fmaf(p, f, 2.4022651e-1f);
    p = fmaf(p, f, 6.9314718e-1f);
    p = fmaf(p, f, 1.0f);
    return __int_as_float(((int)n + 127) << 23) * p;
}
__device__ __forceinline__ float tanh_fast(float x) {
    float e = exp2_fast(x * 2.885390081777927f);
    return 1.f - 2.f / (e + 1.f);
}
__device__ __forceinline__ float sigmoid_fast(float x) {
    float e = exp2_fast(-1.4426950408889634f * x);
    return 1.f / (1.f + e);
}

// grid-wide barrier
__device__ __forceinline__ void gsync(unsigned& tgt) {
    __syncthreads();
    if (threadIdx.x == 0) {
        __threadfence();
        unsigned v = atomicAdd(&g_bar_count, 1u);
        if (v == NBLK - 1) {
            g_bar_count = 0;
            asm volatile("st.release.gpu.u32 [%0], %1;" :: "l"(&g_bar_phase), "r"(tgt) : "memory");
        } else {
            unsigned p;
            do {
                asm volatile("ld.acquire.gpu.u32 %0, [%1];" : "=r"(p) : "l"(&g_bar_phase) : "memory");
            } while ((int)(p - tgt) < 0);
        }
    }
    __syncthreads();
    tgt++;
}

// ---------------- the persistent mega-kernel ----------------
__global__ __launch_bounds__(NTHR, 2) void k_mega(
    const float* __restrict__ hidden, const float* __restrict__ emb,
    const float* __restrict__ emb_table,
    const float* __restrict__ W_ih, const float* __restrict__ W_hh,
    const float* __restrict__ b_ih, const float* __restrict__ b_hh,
    const float* __restrict__ We, const float* __restrict__ Wq,
    const float* __restrict__ ba, const float* __restrict__ va,
    const float* __restrict__ Wout, const float* __restrict__ bout,
    float* __restrict__ out)
{
    __shared__ __align__(16) float s_As[128 * 36];   // eproj A tile; reused as merge vec
    __shared__ __align__(16) float s_Bs[64 * 33];    // eproj B tile
    __shared__ float s_gru[4][4][6];
    __shared__ float s_red[16];
    __shared__ int s_cand[32];
    __shared__ int s_cnt;
    __shared__ int s_word;

    const int tid = threadIdx.x;
    const int blk = blockIdx.x;
    const int w = tid >> 5, lane = tid & 31;
    const int gw = blk * 16 + w;

    unsigned tgt = *((volatile unsigned*)&g_bar_phase) + 1;

    // ---------- phase 0a: init + quant (all blocks) ----------
    if (blk == 0 && tid < 2) { g_M[tid] = 0u; g_best[tid] = 0ull; }
    if (blk == 1) {
        for (int i = tid; i < HDIM; i += NTHR) g_h[0][i] = hidden[i];
    }
    {
        const size_t n8 = (size_t)VDIM * MERGED / 8;
        for (size_t idx = (size_t)blk * NTHR + tid; idx < n8; idx += (size_t)NBLK * NTHR) {
            const float4* p = (const float4*)Wout + idx * 2;
            float4 a = __ldcs(p);
            float4 b = __ldcs(p + 1);
            uint4 o;
            *(__nv_bfloat162*)&o.x = __nv_bfloat162(__float2bfloat16(a.x), __float2bfloat16(a.y));
            *(__nv_bfloat162*)&o.y = __nv_bfloat162(__float2bfloat16(a.z), __float2bfloat16(a.w));
            *(__nv_bfloat162*)&o.z = __nv_bfloat162(__float2bfloat16(b.x), __float2bfloat16(b.y));
            *(__nv_bfloat162*)&o.w = __nv_bfloat162(__float2bfloat16(b.z), __float2bfloat16(b.w));
            __stcs((uint4*)g_wbf + idx, o);
        }
    }
    gsync(tgt);

    // ---------- phase 0b: eproj (blocks 0-255, one 128x64 tile each) ----------
    if (blk < 256) {
        const int ts0 = (blk >> 4) * 128;
        const int ta0 = (blk & 15) * 64;
        const int ts = tid >> 4;
        const int ta = tid & 15;
        float acc[4][4];
#pragma unroll
        for (int i = 0; i < 4; i++)
#pragma unroll
            for (int j = 0; j < 4; j++) acc[i][j] = 0.f;
        for (int kt = 0; kt < 1024; kt += 32) {
#pragma unroll
            for (int r = 0; r < 8; r++) {
                int e0 = tid + NTHR * r;
                int si = e0 >> 5, kk = e0 & 31;
                s_As[si * 36 + kk] = emb[(size_t)(ts0 + si) * 1024 + kt + kk];
            }
#pragma unroll
            for (int r = 0; r < 4; r++) {
                int e0 = tid + NTHR * r;
                int ai = e0 >> 5, kk = e0 & 31;
                s_Bs[ai * 33 + kk] = We[(size_t)(ta0 + ai) * 1024 + kt + kk];
            }
            __syncthreads();
#pragma unroll
            for (int k = 0; k < 32; k++) {
                float a0 = s_As[ts * 36 + k];
                float a1 = s_As[(ts + 32) * 36 + k];
                float a2 = s_As[(ts + 64) * 36 + k];
                float a3 = s_As[(ts + 96) * 36 + k];
                float b0 = s_Bs[(ta * 4 + 0) * 33 + k];
                float b1 = s_Bs[(ta * 4 + 1) * 33 + k];
                float b2 = s_Bs[(ta * 4 + 2) * 33 + k];
                float b3 = s_Bs[(ta * 4 + 3) * 33 + k];
                acc[0][0] = fmaf(a0, b0, acc[0][0]); acc[0][1] = fmaf(a0, b1, acc[0][1]);
                acc[0][2] = fmaf(a0, b2, acc[0][2]); acc[0][3] = fmaf(a0, b3, acc[0][3]);
                acc[1][0] = fmaf(a1, b0, acc[1][0]); acc[1][1] = fmaf(a1, b1, acc[1][1]);
                acc[1][2] = fmaf(a1, b2, acc[1][2]); acc[1][3] = fmaf(a1, b3, acc[1][3]);
                acc[2][0] = fmaf(a2, b0, acc[2][0]); acc[2][1] = fmaf(a2, b1, acc[2][1]);
                acc[2][2] = fmaf(a2, b2, acc[2][2]); acc[2][3] = fmaf(a2, b3, acc[2][3]);
                acc[3][0] = fmaf(a3, b0, acc[3][0]); acc[3][1] = fmaf(a3, b1, acc[3][1]);
                acc[3][2] = fmaf(a3, b2, acc[3][2]); acc[3][3] = fmaf(a3, b3, acc[3][3]);
            }
            __syncthreads();
        }
        float4 bb = __ldg((const float4*)(ba + ta0) + ta);
#pragma unroll
        for (int i = 0; i < 4; i++) {
            float4 o = make_float4(acc[i][0] + bb.x, acc[i][1] + bb.y,
                                   acc[i][2] + bb.z, acc[i][3] + bb.w);
            *(float4*)&g_eproj[(size_t)(ts0 + ts + 32 * i) * 1024 + ta0 + ta * 4] = o;
        }
    }
    gsync(tgt);

    // ---------- decode loop ----------
    int word = 1;  // SOS
    for (int t = 0; t < NBOUND; t++) {
        const int par = t & 1;
        const int pold = par, pnew = par ^ 1;

        // ---- GRU: 16 warps = 4 rows/block x 4 k-slices ----
        {
            int g = w >> 2, sub = w & 3;
            int j = blk * 4 + g;
            if (j < 1024) {
                int k4 = sub * 64;
                const float4* xv = (const float4*)(emb_table + (size_t)word * 1024) + k4;
                const float4* hv = (const float4*)g_h[pold] + k4;
                const float4* m0 = (const float4*)(W_ih + (size_t)j * 1024) + k4;
                const float4* m1 = (const float4*)(W_ih + (size_t)(1024 + j) * 1024) + k4;
                const float4* m2 = (const float4*)(W_ih + (size_t)(2048 + j) * 1024) + k4;
                const float4* m3 = (const float4*)(W_hh + (size_t)j * 1024) + k4;
                const float4* m4p = (const float4*)(W_hh + (size_t)(1024 + j) * 1024) + k4;
                const float4* m5 = (const float4*)(W_hh + (size_t)(2048 + j) * 1024) + k4;
                float a0 = 0, a1 = 0, a2 = 0, a3 = 0, a4 = 0, a5 = 0;
#pragma unroll
                for (int i = 0; i < 2; i++) {
                    int k = lane + 32 * i;
                    float4 x = __ldg(xv + k);
                    float4 h = __ldcg(hv + k);
                    float4 m;
                    m = __ldg(m0 + k); a0 = fmaf(m.x, x.x, a0); a0 = fmaf(m.y, x.y, a0); a0 = fmaf(m.z, x.z, a0); a0 = fmaf(m.w, x.w, a0);
                    m = __ldg(m1 + k); a1 = fmaf(m.x, x.x, a1); a1 = fmaf(m.y, x.y, a1); a1 = fmaf(m.z, x.z, a1); a1 = fmaf(m.w, x.w, a1);
                    m = __ldg(m2 + k); a2 = fmaf(m.x, x.x, a2); a2 = fmaf(m.y, x.y, a2); a2 = fmaf(m.z, x.z, a2); a2 = fmaf(m.w, x.w, a2);
                    m = __ldg(m3 + k); a3 = fmaf(m.x, h.x, a3); a3 = fmaf(m.y, h.y, a3); a3 = fmaf(m.z, h.z, a3); a3 = fmaf(m.w, h.w, a3);
                    m = __ldg(m4p + k); a4 = fmaf(m.x, h.x, a4); a4 = fmaf(m.y, h.y, a4); a4 = fmaf(m.z, h.z, a4); a4 = fmaf(m.w, h.w, a4);
                    m = __ldg(m5 + k); a5 = fmaf(m.x, h.x, a5); a5 = fmaf(m.y, h.y, a5); a5 = fmaf(m.z, h.z, a5); a5 = fmaf(m.w, h.w, a5);
                }
                a0 = warp_sum(a0); a1 = warp_sum(a1); a2 = warp_sum(a2);
                a3 = warp_sum(a3); a4 = warp_sum(a4); a5 = warp_sum(a5);
                if (lane == 0) {
                    s_gru[g][sub][0] = a0; s_gru[g][sub][1] = a1; s_gru[g][sub][2] = a2;
                    s_gru[g][sub][3] = a3; s_gru[g][sub][4] = a4; s_gru[g][sub][5] = a5;
                }
            }
            __syncthreads();
            if (tid < 4) {
                int jo = blk * 4 + tid;
                if (jo < 1024) {
                    float D[6];
#pragma unroll
                    for (int d = 0; d < 6; d++)
                        D[d] = s_gru[tid][0][d] + s_gru[tid][1][d] + s_gru[tid][2][d] + s_gru[tid][3][d];
                    float gr = D[0] + __ldg(&b_ih[jo]);
                    float gz = D[1] + __ldg(&b_ih[1024 + jo]);
                    float gn = D[2] + __ldg(&b_ih[2048 + jo]);
                    float hr = D[3] + __ldg(&b_hh[jo]);
                    float hz = D[4] + __ldg(&b_hh[1024 + jo]);
                    float hn = D[5] + __ldg(&b_hh[2048 + jo]);
                    float r = sigmoid_fast(gr + hr);
                    float z = sigmoid_fast(gz + hz);
                    float n = tanh_fast(gn + r * hn);
                    float hold = __ldcg(&g_h[pold][jo]);
                    __stcg(&g_h[pnew][jo], (1.f - z) * n + z * hold);
                }
            }
        }
        gsync(tgt);
        if (blk == 0 && tid == 0) {
            atomicExch(&g_M[par ^ 1], 0u);
            atomicExch(&g_best[par ^ 1], 0ull);
        }

        // ---- q[a] = h_new . Wq[a,:] ----
        {
            int a = w * NBLK + blk;
            if (w < 4 && a < 1024) {
                const float4* mq = (const float4*)(Wq + (size_t)a * 1024);
                const float4* hv = (const float4*)g_h[pnew];
                float acc = 0.f;
#pragma unroll
                for (int i = 0; i < 8; i++) {
                    int k = lane + 32 * i;
                    float4 m = __ldg(mq + k);
                    float4 h = __ldcg(hv + k);
                    acc = fmaf(m.x, h.x, acc); acc = fmaf(m.y, h.y, acc);
                    acc = fmaf(m.z, h.z, acc); acc = fmaf(m.w, h.w, acc);
                }
                acc = warp_sum(acc);
                if (lane == 0) __stcg(&g_q[a], acc);
            }
        }
        gsync(tgt);

        // ---- s[j] = sum_a tanh(eproj[j,a] + q[a]) * v_a[a] ----
        {
            int j = w * NBLK + blk;
            if (w < 7 && j < 2048) {
                const float4* ep = (const float4*)(g_eproj + (size_t)j * 1024);
                const float4* qv = (const float4*)g_q;
                const float4* vv = (const float4*)va;
                float acc = 0.f;
#pragma unroll 4
                for (int i = 0; i < 8; i++) {
                    int k = lane + 32 * i;
                    float4 e4 = __ldg(ep + k);
                    float4 q4 = __ldcg(qv + k);
                    float4 v4 = __ldg(vv + k);
                    acc = fmaf(tanh_fast(e4.x + q4.x), v4.x, acc);
                    acc = fmaf(tanh_fast(e4.y + q4.y), v4.y, acc);
                    acc = fmaf(tanh_fast(e4.z + q4.z), v4.z, acc);
                    acc = fmaf(tanh_fast(e4.w + q4.w), v4.w, acc);
                }
                acc = warp_sum(acc);
                if (lane == 0) __stcg(&g_s[j], acc);
            }
        }
        gsync(tgt);

        // ---- softmax (redundant stats) + ctx partials + weights output ----
        if (blk < 128) {
            float v4[4];
            float lm = -3.4e38f;
#pragma unroll
            for (int r = 0; r < 4; r++) {
                v4[r] = __ldcg(&g_s[tid + 512 * r]);
                lm = fmaxf(lm, v4[r]);
            }
#pragma unroll
            for (int o = 16; o; o >>= 1) lm = fmaxf(lm, __shfl_xor_sync(0xffffffffu, lm, o));
            if (lane == 0) s_red[w] = lm;
            __syncthreads();
            float m = s_red[0];
#pragma unroll
            for (int k = 1; k < 16; k++) m = fmaxf(m, s_red[k]);
            __syncthreads();
            float ls = 0.f;
#pragma unroll
            for (int r = 0; r < 4; r++) ls += expf(v4[r] - m);
            ls = warp_sum(ls);
            if (lane == 0) s_red[w] = ls;
            __syncthreads();
            float tot = s_red[0];
#pragma unroll
            for (int k = 1; k < 16; k++) tot += s_red[k];
            float inv = 1.f / tot;

            if (blk == 0) {
                size_t base = (size_t)NBOUND + (size_t)t * SDIM;
#pragma unroll
                for (int r = 0; r < 4; r++)
                    out[base + tid + 512 * r] = expf(v4[r] - m) * inv;
            }

            // ctx partial: s-chunk of 256, a-chunk of 64
            int sc = blk >> 4;        // 0..7
            int ac = blk & 15;        // 0..15
            int a0 = ac * 64;
            int g = tid >> 6, al = tid & 63;
            float acc = 0.f;
            int sb = sc * 256 + g * 32;
            for (int ss = 0; ss < 32; ss++) {
                int s = sb + ss;
                float wv = expf(__ldcg(&g_s[s]) - m) * inv;
                acc = fmaf(wv, __ldg(&emb[(size_t)s * 1024 + a0 + al]), acc);
            }
            float* sred = s_As;
            sred[g * 64 + al] = acc;
            __syncthreads();
            if (tid < 64) {
                float c = 0.f;
#pragma unroll
                for (int gg = 0; gg < 8; gg++) c += sred[gg * 64 + tid];
                __stcg(&g_ctx_part[sc][a0 + tid], c);
            }
        }
        gsync(tgt);

        // ---- vocab: bf16 GEMV + bound (block-local max -> 1 atomic) ----
        float* ms = s_As;
        for (int i = tid; i < 1024; i += NTHR) ms[i] = __ldcg(&g_h[pnew][i]);
        for (int i = tid; i < 1024; i += NTHR) {
            float c = 0.f;
#pragma unroll
            for (int p = 0; p < 8; p++) c += __ldcg(&g_ctx_part[p][i]);
            ms[1024 + i] = c;
        }
        __syncthreads();
        const float4* m4 = (const float4*)ms;
        float wmax = -3.4e38f;
        for (int v = gw; v < VDIM; v += NWTOT) {
            const unsigned long long* r8 =
                (const unsigned long long*)(g_wbf + (size_t)v * MERGED);
            float acc = 0.f, ab = 0.f;
#pragma unroll 8
            for (int i = 0; i < 16; i++) {
                unsigned long long u = __ldcs(r8 + lane + 32 * i);
                float4 mm = m4[lane + 32 * i];
                unsigned lo = (unsigned)u, hi = (unsigned)(u >> 32);
                float2 f0 = __bfloat1622float2(*(__nv_bfloat162*)&lo);
                float2 f1 = __bfloat1622float2(*(__nv_bfloat162*)&hi);
                acc = fmaf(f0.x, mm.x, acc); ab = fmaf(fabsf(f0.x), fabsf(mm.x), ab);
                acc = fmaf(f0.y, mm.y, acc); ab = fmaf(fabsf(f0.y), fabsf(mm.y), ab);
                acc = fmaf(f1.x, mm.z, acc); ab = fmaf(fabsf(f1.x), fabsf(mm.z), ab);
                acc = fmaf(f1.y, mm.w, acc); ab = fmaf(fabsf(f1.y), fabsf(mm.w), ab);
            }
            acc = warp_sum(acc);
            ab = warp_sum(ab);
            if (lane == 0) {
                float A = acc + __ldg(&bout[v]);
                float B = fmaf(ab, 0.00390625f, 1e-4f);
                __stcg(&g_ub[v], A + B);
                wmax = fmaxf(wmax, A - B);
            }
        }
#pragma unroll
        for (int o = 16; o; o >>= 1) wmax = fmaxf(wmax, __shfl_xor_sync(0xffffffffu, wmax, o));
        if (lane == 0) s_red[w] = wmax;
        __syncthreads();
        if (tid == 0) {
            float bm = s_red[0];
#pragma unroll
            for (int k = 1; k < 16; k++) bm = fmaxf(bm, s_red[k]);
            atomicMax(&g_M[par], enc_f(bm));
        }
        gsync(tgt);

        // ---- scan + exact fp32 rescore ----
        if (tid == 0) s_cnt = 0;
        __syncthreads();
        {
            float thr = dec_f(__ldcg(&g_M[par]));
            int i = blk * NTHR + tid;
            if (i < VDIM && __ldcg(&g_ub[i]) >= thr) {
                int p = atomicAdd(&s_cnt, 1);
                if (p < 32) s_cand[p] = i;
            }
        }
        __syncthreads();
        int nc = min(s_cnt, 32);
        for (int c = 0; c < nc; c++) {
            int v = s_cand[c];
            float4 rr = __ldg((const float4*)(Wout + (size_t)v * MERGED) + tid);
            float4 mm = m4[tid];
            float a = fmaf(rr.x, mm.x, fmaf(rr.y, mm.y, fmaf(rr.z, mm.z, rr.w * mm.w)));
            a = warp_sum(a);
            if (lane == 0) s_red[w] = a;
            __syncthreads();
            if (tid == 0) {
                float L = 0.f;
#pragma unroll
                for (int k = 0; k < 16; k++) L += s_red[k];
                L += __ldg(&bout[v]);
                unsigned long long pk =
                    ((unsigned long long)enc_f(L) << 32) |
                    (unsigned long long)(0xFFFFFFFFu - (unsigned)v);
                atomicMax(&g_best[par], pk);
            }
            __syncthreads();
        }
        gsync(tgt);

        if (tid == 0) {
            unsigned long long pk = __ldcg(&g_best[par]);
            int wd = (int)(0xFFFFFFFFu - (unsigned)(pk & 0xFFFFFFFFull));
            s_word = wd;
            if (blk == 0) out[t] = (float)wd;
        }
        __syncthreads();
        word = s_word;
    }
}

// ---------------- launch ----------------
extern "C" void kernel_launch(void* const* d_in, const int* in_sizes, int n_in,
                              void* d_out, int out_size) {
    const float* hidden     = (const float*)d_in[0];
    const float* embeddings = (const float*)d_in[1];
    const float* emb_table  = (const float*)d_in[2];
    const float* W_ih       = (const float*)d_in[3];
    const float* W_hh       = (const float*)d_in[4];
    const float* b_ih       = (const float*)d_in[5];
    const float* b_hh       = (const float*)d_in[6];
    const float* W_e        = (const float*)d_in[7];
    const float* W_q        = (const float*)d_in[8];
    const float* b_a        = (const float*)d_in[9];
    const float* v_a        = (const float*)d_in[10];
    const float* W_out      = (const float*)d_in[11];
    const float* b_out      = (const float*)d_in[12];
    float* out = (float*)d_out;

    k_mega<<<NBLK, NTHR>>>(hidden, embeddings, emb_table, W_ih, W_hh, b_ih, b_hh,
                           W_e, W_q, b_a, v_a, W_out, b_out, out);
}